// round 9
// baseline (speedup 1.0000x reference)
#include <cuda_runtime.h>

#define HID  128
#define MH   64
#define D32  32
#define OUTD 128
#define NB   128   // k1/k3 grid; 8 rows per block

// ---- device globals (no allocation allowed) ----
__device__ float g_part[NB * 128]; // [b][0:64)=hid, [64:96)=a, [96:128)=c
__device__ float g_final[192];     // [0:32)=S, [32:64)=T, [64:192)=K
__device__ float g_dummy[512];     // sink for L2-warm prefetch
__device__ int   g_cnt;            // ticket; reset by reducer each replay

// ========== k1: smem-staged hidden GEMM + partials; last block reduces ==========
__global__ void __launch_bounds__(512) k1(
    const float* __restrict__ hs,
    const float* __restrict__ obs1,
    const float* __restrict__ obs,
    const float* __restrict__ W_sp,
    const float* __restrict__ b_sp,
    const float* __restrict__ W_vel,
    const float* __restrict__ b_vel,
    const float* __restrict__ W_hid,
    const float* __restrict__ b_hid,
    const float* __restrict__ W_out,
    const float* __restrict__ b_out)
{
    __shared__ float wS[HID][MH];   // 32 KB, [c][k]; tail scratch aliases here
    __shared__ float hsS[8][HID];   // 4 KB
    __shared__ float bhS[MH];
    __shared__ float sa[8][D32];    // 1 KB
    __shared__ float sc[8][D32];    // 1 KB
    __shared__ float p0[8][MH];     // 2 KB
    __shared__ float p1[8][MH];     // 2 KB
    __shared__ float red[4][MH];    // 1 KB
    __shared__ int   isLast;

    int b = blockIdx.x, t = threadIdx.x;
    int row0 = b * 8;

    // ---- staging: ALL loads independent, one latency wave ----
    #pragma unroll
    for (int j = 0; j < 4; j++)     // W_hid: 2048 float4, 4 per thread
        ((float4*)wS)[t + 512 * j] = ((const float4*)W_hid)[t + 512 * j];

    if (t < 64) bhS[t] = b_hid[t];

    if (t < 256) {                  // hs tile: 256 float4
        ((float4*)hsS)[t] = ((const float4*)(hs + row0 * HID))[t];
    } else {                        // projections: row = tt>>5, d = tt&31
        int tt = t - 256;
        int row = tt >> 5, d = tt & 31;
        int i = row0 + row;
        float2 oo = ((const float2*)obs)[i];
        float2 o1 = ((const float2*)obs1)[i];
        sa[row][d] = fmaf(oo.x, W_sp[d], oo.y * W_sp[D32 + d]);
        float vx = 4.f * (oo.x - o1.x), vy = 4.f * (oo.y - o1.y);
        sc[row][d] = fmaf(vx, W_vel[d], vy * W_vel[D32 + d]);
    }
    __syncthreads();

    {   // GEMM from smem: 512 thr = k(64) x ch(2 c-halves) x rg(4 row-pairs)
        int k = t & 63, g = t >> 6;          // g = rg*2 + ch
        int ch = g & 1, rg = g >> 1;
        const float* wp = &wS[ch * 64][k];   // bank = k%32 (conflict-free)
        const float* h0 = &hsS[rg * 2][ch * 64];
        const float* h1 = &hsS[rg * 2 + 1][ch * 64];
        float a0 = 0.f, a1 = 0.f;
        #pragma unroll
        for (int c = 0; c < 64; c++) {
            float w = wp[c * MH];
            a0 = fmaf(h0[c], w, a0);         // smem broadcast
            a1 = fmaf(h1[c], w, a1);
        }
        p0[g][k] = a0;
        p1[g][k] = a1;
    }
    __syncthreads();

    if (t < 256) {                  // combine c-halves, relu, max over 2 rows
        int k = t & 63, rg = t >> 6;
        float bk = bhS[k];
        float a0 = bk + p0[rg * 2][k] + p0[rg * 2 + 1][k];
        float a1 = bk + p1[rg * 2][k] + p1[rg * 2 + 1][k];
        red[rg][k] = fmaxf(fmaxf(a0, a1), 0.f);
    }
    __syncthreads();

    if (t < 64) {
        g_part[b * 128 + t] = fmaxf(fmaxf(red[0][t], red[1][t]),
                                    fmaxf(red[2][t], red[3][t]));
    } else if (t < 96) {
        int d = t - 64;
        float m = sa[0][d];
        #pragma unroll
        for (int r = 1; r < 8; r++) m = fmaxf(m, sa[r][d]);
        g_part[b * 128 + t] = m;
    } else if (t < 128) {
        int d = t - 96;
        float m = sc[0][d];
        #pragma unroll
        for (int r = 1; r < 8; r++) m = fmaxf(m, sc[r][d]);
        g_part[b * 128 + t] = m;
    }
    __threadfence();
    if (t == 0) isLast = (atomicAdd(&g_cnt, 1) == NB - 1);
    __syncthreads();
    if (!isLast) return;

    // ======= reducer tail (only the LAST-arriving block; others exited) =======
    // scratch aliases into wS (done with weights; two syncs since last read)
    float* red2  = &wS[0][0];        // [4][128] = 512 floats
    float* hmS   = red2 + 512;       // [64]
    float* biasS = hmS + 64;         // [192]
    float* kred  = biasS + 192;      // [4][128] = 512 floats
    __syncthreads();                 // all 512 threads of this block are here

    if (t < 192)                     // biases: independent, same wave as below
        biasS[t] = (t < 32) ? b_sp[t] : (t < 64) ? b_vel[t - 32] : b_out[t - 64];

    {   // reduce NB=128 partials: 128 cols x 4 groups x 32 rows (independent)
        int col = t & 127, grp = t >> 7;
        const float* p = g_part + grp * 32 * 128 + col;
        float m = -3.4e38f;
        #pragma unroll
        for (int q = 0; q < 32; q++) m = fmaxf(m, __ldcg(&p[q * 128]));
        red2[grp * 128 + col] = m;
    }
    {   // warm W_out[0:64] into L2 for k3 (independent, same wave)
        float dummy = 0.f;
        #pragma unroll
        for (int j = 0; j < 16; j++) dummy += __ldg(&W_out[j * 512 + t]);
        g_dummy[t] = dummy;
    }
    __syncthreads();
    if (t < 128) {
        float v = fmaxf(fmaxf(red2[t], red2[128 + t]),
                        fmaxf(red2[256 + t], red2[384 + t]));
        if (t < 64) hmS[t] = v;
        else        g_final[t - 64] = v + biasS[t - 64];   // S then T
    }
    __syncthreads();
    {   // K[o] = b_out[o] + sum_k hm[k]*W_out[64+k][o]; 16 k's per thread
        int o = t & 127, kh = t >> 7;
        float acc = 0.f;
        #pragma unroll
        for (int j = 0; j < 16; j++) {
            int k = kh * 16 + j;
            acc = fmaf(hmS[k], __ldg(&W_out[(64 + k) * OUTD + o]), acc);
        }
        kred[kh * 128 + o] = acc;
    }
    __syncthreads();
    if (t < 128)
        g_final[64 + t] = biasS[64 + t] + kred[t] + kred[128 + t]
                                        + kred[256 + t] + kred[384 + t];
    if (t == 0) g_cnt = 0;          // reset ticket (deterministic replays)
}

// ========== k3: stage W_out[0:64] in one wave, GEMM from smem ==========
__global__ void __launch_bounds__(512) k3(
    const float* __restrict__ obs1,
    const float* __restrict__ obs,
    const float* __restrict__ W_sp,
    const float* __restrict__ W_vel,
    const float* __restrict__ W_out,
    float* __restrict__ out)
{
    __shared__ float woS[64][OUTD];   // 32 KB, [d][o]
    __shared__ float SS[D32], TS[D32], KS[OUTD];
    __shared__ float f[8][MH];        // 2 KB
    __shared__ float part[4][4][128]; // 8 KB
    int b = blockIdx.x, t = threadIdx.x;
    int row0 = b * 8;

    // ---- staging: all independent loads, one wave (L2-hot) ----
    #pragma unroll
    for (int j = 0; j < 4; j++)       // W_out[0:64]: 2048 float4, 4 per thread
        ((float4*)woS)[t + 512 * j] = ((const float4*)W_out)[t + 512 * j];

    int frow = t >> 6, fd = t & 63;
    int fi = row0 + frow;
    float2 oo = ((const float2*)obs)[fi];   // L2-hot (k1 read it)
    float2 o1 = ((const float2*)obs1)[fi];

    if (t < 192) {
        float v = g_final[t];
        if (t < 32)       SS[t] = v;
        else if (t < 64)  TS[t - 32] = v;
        else              KS[t - 64] = v;
    }
    __syncthreads();

    {   // features: 512 slots = 8 rows x 64 d
        float val;
        if (fd < D32) {
            float a = fmaf(oo.x, W_sp[fd], oo.y * W_sp[D32 + fd]);
            val = fmaxf(SS[fd] - a, 0.f);
        } else {
            int dd = fd - D32;
            float vx = 4.f * (oo.x - o1.x), vy = 4.f * (oo.y - o1.y);
            float c = fmaf(vx, W_vel[dd], vy * W_vel[D32 + dd]);
            val = fmaxf(TS[dd] - c, 0.f);
        }
        f[frow][fd] = val;
    }
    __syncthreads();

    {   // GEMM from smem: 512 thr = o(128) x ch(2 d-halves) x rh(2 row-quads)
        int o = t & 127, g = t >> 7;  // g = rh*2 + ch
        int ch = g & 1, rh = g >> 1;
        const float* wp = &woS[ch * 32][o];  // bank = o%32 (conflict-free)
        float acc[4] = {0.f, 0.f, 0.f, 0.f};
        #pragma unroll
        for (int d = 0; d < 32; d++) {
            float w = wp[d * OUTD];
            #pragma unroll
            for (int r = 0; r < 4; r++)
                acc[r] = fmaf(f[rh * 4 + r][ch * 32 + d], w, acc[r]); // broadcast
        }
        #pragma unroll
        for (int r = 0; r < 4; r++) part[g][r][o] = acc[r];
    }
    __syncthreads();

    {   // combine d-halves + K, write out: 1024 outputs, 2 per thread
        #pragma unroll
        for (int s = 0; s < 2; s++) {
            int slot = t + 512 * s;
            int row = slot >> 7, o = slot & 127;
            int rh = row >> 2, r = row & 3;
            out[(row0 + row) * OUTD + o] =
                KS[o] + part[rh * 2][r][o] + part[rh * 2 + 1][r][o];
        }
    }
}

extern "C" void kernel_launch(void* const* d_in, const int* in_sizes, int n_in,
                              void* d_out, int out_size)
{
    const float* hs    = (const float*)d_in[0];
    const float* obs1  = (const float*)d_in[1];
    const float* obs   = (const float*)d_in[2];
    const float* W_sp  = (const float*)d_in[3];
    const float* b_sp  = (const float*)d_in[4];
    const float* W_vel = (const float*)d_in[5];
    const float* b_vel = (const float*)d_in[6];
    const float* W_hid = (const float*)d_in[7];
    const float* b_hid = (const float*)d_in[8];
    const float* W_out = (const float*)d_in[9];
    const float* b_out = (const float*)d_in[10];
    float* out = (float*)d_out;

    k1<<<NB, 512>>>(hs, obs1, obs, W_sp, b_sp, W_vel, b_vel,
                    W_hid, b_hid, W_out, b_out);
    k3<<<NB, 512>>>(obs1, obs, W_sp, W_vel, W_out, out);
}